// round 16
// baseline (speedup 1.0000x reference)
#include <cuda_runtime.h>
#include <cuda_fp16.h>
#include <stdint.h>

#define N_NODES 50000
#define N_EDGES 1600000
#define F_IN 128
#define F_H  64
#define F_OUT 32
#define SCAN_BLK 1024

// ---------------- device scratch (no allocations allowed) ----------------
__device__ int     g_is64;
__device__ int     g_eisel;
__device__ int     g_done;                    // scan1 completion counter
__device__ int     g_rank[N_EDGES];           // per-edge rank within its col
__device__ int     g_cnt[N_NODES];
__device__ int     g_off[N_NODES + 1];        // block-LOCAL exclusive offsets
__device__ int     g_bsum[64];                // exclusive block offsets (after scan1)
__device__ float   g_dinv[N_NODES];
__device__ __half  g_dinv16[N_NODES];
__device__ int     g_csr[N_EDGES];            // row (16b) | dinv[row] fp16 (16b)
__device__ __half2 g_h0[N_NODES * (F_H / 2)]; // x @ W1          (UNscaled fp16)
__device__ __half2 g_h [N_NODES * (F_H / 2)]; // dinv * relu(l1) (pre-scaled fp16)

// packed fp32x2 FMA (Blackwell FFMA2) helpers
__device__ __forceinline__ unsigned long long pack2(float lo, float hi) {
    unsigned long long r;
    asm("mov.b64 %0, {%1, %2};" : "=l"(r) : "r"(__float_as_uint(lo)), "r"(__float_as_uint(hi)));
    return r;
}
__device__ __forceinline__ void fma2(unsigned long long& acc, unsigned long long a,
                                     unsigned long long b) {
    asm("fma.rn.f32x2 %0, %1, %2, %0;" : "+l"(acc) : "l"(a), "l"(b));
}
__device__ __forceinline__ float lo2(unsigned long long v) {
    return __uint_as_float((unsigned)(v & 0xFFFFFFFFull));
}
__device__ __forceinline__ float hi2(unsigned long long v) {
    return __uint_as_float((unsigned)(v >> 32));
}

// ---------------- probe only (tiny, first) ----------------
__global__ void k_probe(const int* __restrict__ c0, const int* __restrict__ c1,
                        int tie, int host_eisel) {
    int lane = threadIdx.x;
    if (lane == 0) g_done = 0;
    if (tie) {
        int any0 = 0;
        for (int k = 1 + 2 * lane; k < 2048; k += 64) any0 |= c0[k];
        any0 = __any_sync(0xffffffffu, any0 != 0);
        if (lane == 0) { g_eisel = any0 ? 1 : 0; g_is64 = 1; }
    } else {
        const int* w = host_eisel ? c1 : c0;
        int any = 0;
        for (int k = 1 + 2 * lane; k < 2048; k += 64) any |= w[k];
        any = __any_sync(0xffffffffu, any != 0);
        if (lane == 0) { g_eisel = host_eisel; g_is64 = any ? 0 : 1; }
    }
}

// ---------------- zero counts ----------------
__global__ void k_zero(int n) {
    int i = blockIdx.x * blockDim.x + threadIdx.x;
    if (i < n) g_cnt[i] = 0;
}

// ---------------- pass 1: count cols + edge rank (reads col half only) ----------------
__global__ void k_count(const void* __restrict__ c0, const void* __restrict__ c1,
                        int e, int n) {
    int i = blockIdx.x * blockDim.x + threadIdx.x;
    if (i >= e) return;
    const void* p = g_eisel ? c1 : c0;
    int c;
    if (g_is64) c = (int)((const long long*)p)[e + i];
    else        c = ((const int*)p)[e + i];
    if ((unsigned)c >= (unsigned)n) c = 0;
    g_rank[i] = atomicAdd(&g_cnt[c], 1);
}

// ---------------- scan (block-local) + dinv (f32 + f16) + last-block sum scan ----------
__global__ void k_scan1(int n, int nb) {
    __shared__ int s[SCAN_BLK];
    __shared__ int is_last;
    int t = threadIdx.x;
    int i = blockIdx.x * SCAN_BLK + t;
    int v = (i < n) ? g_cnt[i] : 0;
    s[t] = v;
    __syncthreads();
    for (int d = 1; d < SCAN_BLK; d <<= 1) {
        int u = (t >= d) ? s[t - d] : 0;
        __syncthreads();
        s[t] += u;
        __syncthreads();
    }
    if (i < n) {
        g_off[i] = s[t] - v;                      // block-local exclusive
        float dv = rsqrtf((float)v + 1.0f);
        g_dinv[i]   = dv;
        g_dinv16[i] = __float2half_rn(dv);
    }
    if (t == SCAN_BLK - 1) g_bsum[blockIdx.x] = s[t];   // block total
    __threadfence();
    __syncthreads();
    if (t == 0) is_last = (atomicAdd(&g_done, 1) == nb - 1) ? 1 : 0;
    __syncthreads();
    if (is_last) {                                // block-uniform: barriers legal
        int bv = (t < nb) ? g_bsum[t] : 0;
        s[t] = bv;
        __syncthreads();
        if (t == 0) {
            int run = 0;
            for (int k = 0; k < nb; k++) {
                int val = s[k];
                s[k] = run;                        // exclusive
                run += val;
            }
        }
        __syncthreads();
        if (t < nb) g_bsum[t] = s[t];              // exclusive block offsets
        if (t == nb - 1) g_off[n] = bv;            // last block's LOCAL total
    }
}

// ---------------- pass 2: fill packed CSR (row | dinv16<<16) ----------------
__global__ void k_fill(const void* __restrict__ c0, const void* __restrict__ c1,
                       int e, int n) {
    int i = blockIdx.x * blockDim.x + threadIdx.x;
    if (i >= e) return;
    const void* p = g_eisel ? c1 : c0;
    int r, c;
    if (g_is64) {
        const long long* q = (const long long*)p;
        r = (int)q[i];
        c = (int)q[e + i];
    } else {
        const int* q = (const int*)p;
        r = q[i];
        c = q[e + i];
    }
    if ((unsigned)r >= (unsigned)n) r = 0;
    if ((unsigned)c >= (unsigned)n) c = 0;
    int off = g_off[c] + __ldg(&g_bsum[c >> 10]);
    unsigned short d16 = __half_as_ushort(__ldg(&g_dinv16[r]));
    g_csr[off + g_rank[i]] = r | ((int)d16 << 16);
}

// ---------------- h0 = x@W1 (UNscaled): no dinv dependency -> full overlap ----------
// 128 nodes/block; tx (0..31) -> feature pair (2tx,2tx+1) via one LDG.64 of W1.
__global__ void k_gemm1(const float* __restrict__ c0, const float* __restrict__ c1,
                        const float* __restrict__ W1, int n) {
    __shared__ __align__(16) float xsT[F_IN][132];   // [k][node], 16B-aligned rows
    const float* x = g_eisel ? c0 : c1;
    int tid = threadIdx.x;                 // 256 threads
    int tx = tid & 31;                     // feature pair index
    int ty = tid >> 5;                     // 0..7 : node group of 16
    int node0 = blockIdx.x * 128;
    for (int idx = tid; idx < 128 * F_IN; idx += 256) {
        int nd = idx >> 7;
        int k  = idx & 127;
        int node = node0 + nd;
        xsT[k][nd] = (node < n) ? x[(size_t)node * F_IN + k] : 0.0f;
    }
    __syncthreads();
    unsigned long long acc0[8] = {0,0,0,0,0,0,0,0};
    unsigned long long acc1[8] = {0,0,0,0,0,0,0,0};
    int nb = ty * 16;
    const float2* Wp = (const float2*)W1;
#pragma unroll 4
    for (int k = 0; k < F_IN; k++) {
        float2 w = __ldg(&Wp[k * 32 + tx]);
        unsigned long long w20 = pack2(w.x, w.x);
        unsigned long long w21 = pack2(w.y, w.y);
#pragma unroll
        for (int p = 0; p < 4; p++) {
            ulonglong2 v = *(const ulonglong2*)&xsT[k][nb + 4 * p];
            fma2(acc0[2 * p],     v.x, w20);
            fma2(acc0[2 * p + 1], v.y, w20);
            fma2(acc1[2 * p],     v.x, w21);
            fma2(acc1[2 * p + 1], v.y, w21);
        }
    }
#pragma unroll
    for (int j = 0; j < 8; j++) {
        int n_lo = node0 + nb + 2 * j;
        int n_hi = n_lo + 1;
        if (n_lo < n) g_h0[n_lo * 32 + tx] = __floats2half2_rn(lo2(acc0[j]), lo2(acc1[j]));
        if (n_hi < n) g_h0[n_hi * 32 + tx] = __floats2half2_rn(hi2(acc0[j]), hi2(acc1[j]));
    }
}

// ---------------- gather1: h' = dinv * relu(dinv*(sum dinv_r*h0[r]) + own*dinv + b) --
// lane holds features (2*lane, 2*lane+1); CSR entry carries dinv[row] fp16.
__global__ void k_gather1(const float* __restrict__ bias, int n) {
    int warp = (blockIdx.x * blockDim.x + threadIdx.x) >> 5;
    int lane = threadIdx.x & 31;
    if (warp >= n) return;
    float di = g_dinv[warp];
    float2 own = __half22float2(g_h0[warp * 32 + lane]);
    float a0 = own.x * di, a1 = own.y * di;    // own term scaled by dinv_i (becomes di^2 after final mul)
    int s = g_off[warp]     + __ldg(&g_bsum[warp >> 10]);
    int e = g_off[warp + 1] + __ldg(&g_bsum[(warp + 1) >> 10]);
    for (int j = s; j < e; j += 32) {
        int cnt = e - j; if (cnt > 32) cnt = 32;
        int m = (lane < cnt) ? __ldg(&g_csr[j + lane]) : 0;
#pragma unroll 4
        for (int t = 0; t < cnt; t++) {
            int mm = __shfl_sync(0xffffffffu, m, t);
            int rr = mm & 0xFFFF;
            float w = __half2float(__ushort_as_half((unsigned short)((unsigned)mm >> 16)));
            float2 f = __half22float2(__ldg(&g_h0[rr * 32 + lane]));
            a0 = fmaf(f.x, w, a0);
            a1 = fmaf(f.y, w, a1);
        }
    }
    float2 b = ((const float2*)bias)[lane];
    a0 = fmaxf(fmaf(a0, di, b.x), 0.0f);
    a1 = fmaxf(fmaf(a1, di, b.y), 0.0f);
    g_h[warp * 32 + lane] = __floats2half2_rn(a0 * di, a1 * di);   // pre-scaled for layer 2
}

// ---------------- gather2 + output heads (fused, grid-strided) ----------------
// g_h is pre-scaled; per-edge contribution is a plain add (row extracted from packed CSR)
__global__ void k_g2out(const float* __restrict__ Wmu, const float* __restrict__ bmu,
                        const float* __restrict__ Wls, const float* __restrict__ bls,
                        float* __restrict__ out, int n) {
    __shared__ float Wm[F_H * F_OUT];   // 8 KB
    __shared__ float Wl[F_H * F_OUT];   // 8 KB
    int tid = threadIdx.x;
    int lane = tid & 31;
    for (int i = tid; i < F_H * F_OUT; i += 256) { Wm[i] = Wmu[i]; Wl[i] = Wls[i]; }
    __syncthreads();
    float bm = bmu[lane], bl = bls[lane];
    int gw = blockIdx.x * 8 + (tid >> 5);
    int stride = gridDim.x * 8;
    for (int node = gw; node < n; node += stride) {
        float di = g_dinv[node];
        float2 own = __half22float2(g_h[node * 32 + lane]);
        float a0 = own.x, a1 = own.y;    // features 2*lane, 2*lane+1
        int s = g_off[node]     + __ldg(&g_bsum[node >> 10]);
        int e = g_off[node + 1] + __ldg(&g_bsum[(node + 1) >> 10]);
        for (int j = s; j < e; j += 32) {
            int cnt = e - j; if (cnt > 32) cnt = 32;
            int m = (lane < cnt) ? __ldg(&g_csr[j + lane]) : 0;
#pragma unroll 4
            for (int t = 0; t < cnt; t++) {
                int rr = __shfl_sync(0xffffffffu, m, t) & 0xFFFF;
                float2 f = __half22float2(__ldg(&g_h[rr * 32 + lane]));
                a0 += f.x;
                a1 += f.y;
            }
        }
        a0 *= di;   // g feature 2*lane
        a1 *= di;   // g feature 2*lane+1
        float mu = 0.0f, ls = 0.0f;
#pragma unroll
        for (int k = 0; k < 32; k++) {
            float gx = __shfl_sync(0xffffffffu, a0, k);   // feature 2k
            float gy = __shfl_sync(0xffffffffu, a1, k);   // feature 2k+1
            mu = fmaf(gx, Wm[(2 * k)     * F_OUT + lane], mu);
            mu = fmaf(gy, Wm[(2 * k + 1) * F_OUT + lane], mu);
            ls = fmaf(gx, Wl[(2 * k)     * F_OUT + lane], ls);
            ls = fmaf(gy, Wl[(2 * k + 1) * F_OUT + lane], ls);
        }
        out[(size_t)node * F_OUT + lane]                        = mu + bm;
        out[(size_t)n * F_OUT + (size_t)node * F_OUT + lane]    = ls + bl;
    }
}

// ---------------- launch ----------------
extern "C" void kernel_launch(void* const* d_in, const int* in_sizes, int n_in,
                              void* d_out, int out_size) {
    int n = out_size / (2 * F_OUT);

    long long best1 = -1, best2 = -1; int i1 = -1, i2 = -1;
    for (int i = 0; i < n_in; i++) {
        long long s = in_sizes[i];
        if (s > best1) { best2 = best1; i2 = i1; best1 = s; i1 = i; }
        else if (s > best2) { best2 = s; i2 = i; }
    }
    int tie = (best1 == best2);

    int idx_W1 = -1, idx_b1 = -1;
    int idx_W_a = -1, idx_W_b = -1, idx_b_a = -1, idx_b_b = -1;
    for (int i = 0; i < n_in; i++) {
        if (i == i1 || i == i2) continue;
        int s = in_sizes[i];
        if (s == F_IN * F_H) idx_W1 = i;
        else if (s == F_H) idx_b1 = i;
        else if (s == F_H * F_OUT) { if (idx_W_a < 0) idx_W_a = i; else idx_W_b = i; }
        else if (s == F_OUT) { if (idx_b_a < 0) idx_b_a = i; else idx_b_b = i; }
    }
    int min_big = (i1 < i2) ? i1 : i2;
    int mu_first = (min_big == 0) ? 1 : 0;
    int idx_Wmu = mu_first ? idx_W_a : idx_W_b;
    int idx_Wls = mu_first ? idx_W_b : idx_W_a;
    int idx_bmu = mu_first ? idx_b_a : idx_b_b;
    int idx_bls = mu_first ? idx_b_b : idx_b_a;

    int ca = (i1 < i2) ? i1 : i2;
    int cb = (i1 < i2) ? i2 : i1;
    const float* c0 = (const float*)d_in[ca];
    const float* c1 = (const float*)d_in[cb];

    int e, host_eisel = 0;
    if (tie) {
        e = in_sizes[ca] / 4;
        if (n <= 0) n = in_sizes[ca] / F_IN;
    } else {
        int idx_x  = (in_sizes[ca] > in_sizes[cb]) ? ca : cb;
        int idx_ei = (idx_x == ca) ? cb : ca;
        e = in_sizes[idx_ei] / 2;
        host_eisel = (idx_ei == cb) ? 1 : 0;
        if (n <= 0) n = in_sizes[idx_x] / F_IN;
    }
    if (n > N_NODES) n = N_NODES;
    if (e > N_EDGES) e = N_EDGES;

    const float* W1  = (const float*)d_in[idx_W1];
    const float* b1  = (const float*)d_in[idx_b1];
    const float* Wmu = (const float*)d_in[idx_Wmu];
    const float* bmu = (const float*)d_in[idx_bmu];
    const float* Wls = (const float*)d_in[idx_Wls];
    const float* bls = (const float*)d_in[idx_bls];
    float* out = (float*)d_out;

    // fork-join side stream (created once on first, non-captured, call)
    static cudaStream_t s2 = nullptr;
    static cudaEvent_t ev_fork = nullptr, ev_join = nullptr;
    if (s2 == nullptr) {
        cudaStreamCreateWithFlags(&s2, cudaStreamNonBlocking);
        cudaEventCreateWithFlags(&ev_fork, cudaEventDisableTiming);
        cudaEventCreateWithFlags(&ev_join, cudaEventDisableTiming);
    }

    int nb = (n + SCAN_BLK - 1) / SCAN_BLK;

    // probe first (tiny), then gemm1 forks off with NO other dependencies
    k_probe<<<1, 32>>>((const int*)c0, (const int*)c1, tie, host_eisel);
    cudaEventRecord(ev_fork, 0);
    cudaStreamWaitEvent(s2, ev_fork, 0);
    k_gemm1<<<(n + 127) / 128, 256, 0, s2>>>(c0, c1, W1, n);

    // CSR build chain on main stream, overlapped with gemm1
    k_zero <<<(n + 255) / 256, 256>>>(n);
    k_count<<<(e + 255) / 256, 256>>>((const void*)c0, (const void*)c1, e, n);
    k_scan1<<<nb, SCAN_BLK>>>(n, nb);
    k_fill <<<(e + 255) / 256, 256>>>((const void*)c0, (const void*)c1, e, n);

    // join: gather1 needs both gemm1 (h0) and fill (CSR)
    cudaEventRecord(ev_join, s2);
    cudaStreamWaitEvent(0, ev_join, 0);

    k_gather1<<<(n + 7) / 8, 256>>>(b1, n);
    k_g2out  <<<1184, 256>>>(Wmu, bmu, Wls, bls, out, n);
}